// round 14
// baseline (speedup 1.0000x reference)
#include <cuda_runtime.h>
#include <cuda_fp16.h>
#include <math.h>

namespace {
constexpr int kB = 32, kC = 192, kH = 56, kW = 56;
constexpr int kHeads = 6, kD = 32, kWS = 7, kShift = 3, kHid = 768;
constexpr int kNWin = kB * 8 * 8;   // 2048 windows
constexpr int kTok = kWS * kWS;     // 49
constexpr int kNT = kNWin * kTok;   // 100352 tokens
constexpr int kHWp = kH * kW;       // 3136
}

// ---------------- scratch (static __device__, allocation-free) ----------------
__device__ __half g_wf1[1327104];               // conv1 w fp16 tiles [cc][ocb][72][128]
__device__ __half g_wf2[1327104];               // conv2 w fp16 tiles
__device__ __half g_wq[3 * kC * kC];            // qkv w fp16 tiles [nb][cc][kp][128]
__device__ __half g_wp[kC * kC];                // proj w fp16 tiles
__device__ __half g_xw[(size_t)kNT * kC];       // LN1 out fp16, [win][tok][c]
__device__ float g_q [(size_t)kNT * kC];
__device__ float g_kk[(size_t)kNT * kC];
__device__ float g_vv[(size_t)kNT * kC];
__device__ __half g_ao[(size_t)kNT * kC];       // attn out fp16, [win][tok][c]
__device__ float g_x1[(size_t)kNT * kC];        // x + attn branch (NCHW)
__device__ __half g_h0[(size_t)kNT * kC];       // LN2 out, NHWC fp16
__device__ __half g_h1[(size_t)kNT * kHid];     // conv1+gelu out, NHWC fp16

// ---------------- helpers ----------------------------------------------------
__device__ __forceinline__ void mma_f16(float* d, const unsigned* a, const unsigned* b) {
    asm volatile(
        "mma.sync.aligned.m16n8k16.row.col.f32.f16.f16.f32 "
        "{%0,%1,%2,%3}, {%4,%5,%6,%7}, {%8,%9}, {%0,%1,%2,%3};\n"
        : "+f"(d[0]), "+f"(d[1]), "+f"(d[2]), "+f"(d[3])
        : "r"(a[0]), "r"(a[1]), "r"(a[2]), "r"(a[3]), "r"(b[0]), "r"(b[1]));
}
__device__ __forceinline__ void cp4(unsigned dst, const void* src, int sz) {
    asm volatile("cp.async.ca.shared.global [%0], [%1], 4, %2;" :: "r"(dst), "l"(src), "r"(sz));
}
__device__ __forceinline__ void cp16(unsigned dst, const void* src) {
    asm volatile("cp.async.cg.shared.global [%0], [%1], 16;" :: "r"(dst), "l"(src));
}

// ---------------- conv weight prep (unchanged) --------------------------------
template<int PH>
__global__ void wprep_kernel(const float* __restrict__ w) {
    constexpr int IC = (PH == 0) ? kC : kHid;
    constexpr int OC = (PH == 0) ? kHid : kC;
    constexpr int OCB = OC / 64;
    constexpr int TOT = (IC / 16) * OCB * 9216;
    __half* dst = (PH == 0) ? g_wf1 : g_wf2;
    int i = blockIdx.x * 256 + threadIdx.x;
    if (i >= TOT) return;
    int blk = i / 9216, rem = i - blk * 9216;
    int cc = blk / OCB, ocb = blk - cc * OCB;
    int row = rem >> 7, e = rem & 127;
    int kp = row / 9, tap = row - kp * 9;
    int n = e >> 1, lo = e & 1;
    int o = ocb * 64 + n, ic = cc * 16 + kp * 2 + lo;
    dst[i] = __float2half(w[((size_t)o * IC + ic) * 9 + tap]);
}

// ---------------- gemm weight prep (unchanged) --------------------------------
template<int P>
__global__ void wprep_gemm_kernel(const float* __restrict__ w) {
    constexpr int NB = (P == 0) ? 9 : 3;
    constexpr int TOT = NB * 12 * 1024;
    __half* dst = (P == 0) ? g_wq : g_wp;
    int i = blockIdx.x * 256 + threadIdx.x;
    if (i >= TOT) return;
    int blk = i >> 10, rem = i & 1023;
    int nb = blk / 12, cc = blk - nb * 12;
    int kp = rem >> 7, e = rem & 127;
    int n = e >> 1, lo = e & 1;
    dst[i] = __float2half(w[(size_t)(nb * 64 + n) * kC + cc * 16 + kp * 2 + lo]);
}

// ---------------- LayerNorm (unchanged) ---------------------------------------
template<int MODE>
__global__ void ln_kernel(const float* __restrict__ xin,
                          const float* __restrict__ gam,
                          const float* __restrict__ bet) {
    int p = blockIdx.x * 256 + threadIdx.x;
    if (p >= kNT) return;
    const float* src = (MODE == 0) ? xin : g_x1;
    int b = p / kHWp;
    int rem = p - b * kHWp;
    int hp = rem / kW, wp = rem - (rem / kW) * kW;
    int h = hp, w = wp;
    if (MODE == 0) {
        h = hp + kShift; if (h >= kH) h -= kH;
        w = wp + kShift; if (w >= kW) w -= kW;
    }
    const float* xp = src + ((size_t)b * kC) * kHWp + h * kW + w;
    float s = 0.f, s2 = 0.f;
#pragma unroll 4
    for (int c = 0; c < kC; c++) { float v = xp[(size_t)c * kHWp]; s += v; s2 += v * v; }
    float m = s * (1.f / kC);
    float var = s2 * (1.f / kC) - m * m;
    float rs = rsqrtf(var + 1e-5f);
    if (MODE == 0) {
        int win = b * 64 + (hp / 7) * 8 + (wp / 7);
        int tok = (hp % 7) * 7 + (wp % 7);
        __half* op = g_xw + ((size_t)win * kTok + tok) * kC;
#pragma unroll 4
        for (int c = 0; c < kC; c++) {
            float v = (xp[(size_t)c * kHWp] - m) * rs * gam[c] + bet[c];
            op[c] = __float2half(v);
        }
    } else {
        __half* op = g_h0 + ((size_t)(b * kH + h) * kW + w) * kC;
#pragma unroll 4
        for (int c = 0; c < kC; c++) {
            float v = (xp[(size_t)c * kHWp] - m) * rs * gam[c] + bet[c];
            op[c] = __float2half(v);
        }
    }
}

// ---------------- GEMM fp16 m16n8k16 + cp.async double buffer (R13 winner) ---
template<int EPI>
__global__ __launch_bounds__(128, 2) void gemm_f16_kernel(const float* __restrict__ bias,
                                                          const float* __restrict__ xin) {
    __shared__ unsigned gsm[2 * 3648];
    const __half* A = (EPI == 0) ? g_xw : g_ao;
    const __half* Wg = (EPI == 0) ? g_wq : g_wp;
    const int tid = threadIdx.x;
    const int warp = tid >> 5, lane = tid & 31;
    const int g = lane >> 2, t = lane & 3;
    const int wm = warp;
    const int tokbase = blockIdx.x * 256;
    const int nb = blockIdx.y;
    const int ob = nb * 64;
    const unsigned smem0 = (unsigned)__cvta_generic_to_shared(gsm);

    const int atok = tid >> 1, ahalf = tid & 1;
    const int wrow = tid >> 4, wq = tid & 15;

    auto stage = [&](int cc, int bufi) {
        const unsigned base = smem0 + (unsigned)(bufi * 3648 * 4);
#pragma unroll
        for (int s = 0; s < 4; s++) {
            const int tok = s * 64 + atok;
            cp16(base + (unsigned)((tok * 12 + ahalf * 4) << 2),
                 A + (size_t)(tokbase + tok) * kC + cc * 16 + ahalf * 8);
        }
        cp16(base + (unsigned)((3072 + wrow * 72 + wq * 4) << 2),
             Wg + (size_t)(nb * 12 + cc) * 1024 + wrow * 128 + wq * 8);
        asm volatile("cp.async.commit_group;");
    };

    float acc[4][8][4];
#pragma unroll
    for (int i = 0; i < 4; i++)
#pragma unroll
        for (int j = 0; j < 8; j++)
#pragma unroll
            for (int k = 0; k < 4; k++) acc[i][j][k] = 0.f;

    stage(0, 0);

    for (int cc = 0; cc < 12; cc++) {
        if (cc + 1 < 12) {
            stage(cc + 1, (cc + 1) & 1);
            asm volatile("cp.async.wait_group 1;");
        } else {
            asm volatile("cp.async.wait_group 0;");
        }
        __syncthreads();
        const unsigned* buf = gsm + (cc & 1) * 3648;
        unsigned afr[4][4];
#pragma unroll
        for (int mf = 0; mf < 4; mf++) {
            const int r0 = (wm * 64 + mf * 16 + g) * 12;
            afr[mf][0] = buf[r0 + t];
            afr[mf][1] = buf[r0 + 96 + t];
            afr[mf][2] = buf[r0 + t + 4];
            afr[mf][3] = buf[r0 + 96 + t + 4];
        }
        unsigned bfr[8][2];
#pragma unroll
        for (int nf = 0; nf < 8; nf++) {
            bfr[nf][0] = buf[3072 + t * 72 + nf * 8 + g];
            bfr[nf][1] = buf[3072 + (t + 4) * 72 + nf * 8 + g];
        }
#pragma unroll
        for (int mf = 0; mf < 4; mf++)
#pragma unroll
            for (int nf = 0; nf < 8; nf++)
                mma_f16(acc[mf][nf], afr[mf], bfr[nf]);
        __syncthreads();
    }

#pragma unroll
    for (int mf = 0; mf < 4; mf++) {
        const int tk0 = tokbase + wm * 64 + mf * 16 + g;
#pragma unroll
        for (int nf = 0; nf < 8; nf++) {
            const int o0 = ob + nf * 8 + 2 * t;
            const float bv0 = bias[o0], bv1 = bias[o0 + 1];
            float vals[4] = {acc[mf][nf][0] + bv0, acc[mf][nf][1] + bv1,
                             acc[mf][nf][2] + bv0, acc[mf][nf][3] + bv1};
#pragma unroll
            for (int q = 0; q < 4; q++) {
                const int n_tok = tk0 + (q >> 1) * 8;
                const int mo = o0 + (q & 1);
                const int win = n_tok / 49, tok = n_tok - win * 49;
                if (EPI == 0) {
                    int sec = mo / kC;
                    int c = mo - sec * kC;
                    float* dst = (sec == 0) ? g_q : (sec == 1) ? g_kk : g_vv;
                    dst[((size_t)(win * kHeads + (c >> 5)) * kTok + tok) * kD + (c & 31)] = vals[q];
                } else {
                    int bb  = win >> 6;
                    int whh = (win >> 3) & 7;
                    int www = win & 7;
                    int ti = tok / 7, tj = tok - ti * 7;
                    int hi = whh * 7 + ti + kShift; if (hi >= kH) hi -= kH;
                    int wi = www * 7 + tj + kShift; if (wi >= kW) wi -= kW;
                    size_t idx = ((size_t)(bb * kC + mo) * kH + hi) * kW + wi;
                    g_x1[idx] = xin[idx] + vals[q];
                }
            }
        }
    }
}

// ---------------- attention (unchanged) ---------------------------------------
__global__ __launch_bounds__(64) void attn_kernel() {
    const int wh = blockIdx.x;
    __shared__ float sq[kTok * 33], sk[kTok * kD], sv[kTok * kD];
    const size_t base = (size_t)wh * kTok * kD;
    for (int i = threadIdx.x; i < kTok * kD; i += 64) {
        int r = i >> 5, d = i & 31;
        sq[r * 33 + d] = g_q[base + i];
        sk[i] = g_kk[base + i];
        sv[i] = g_vv[base + i];
    }
    __syncthreads();
    const int r = threadIdx.x;
    if (r < kTok) {
        float qr[kD];
#pragma unroll
        for (int d = 0; d < kD; d++) qr[d] = sq[r * 33 + d];
        float p[kTok];
        float mx = -1e30f;
#pragma unroll
        for (int m = 0; m < kTok; m++) {
            float dot = 0.f;
#pragma unroll
            for (int d = 0; d < kD; d++) dot += qr[d] * sk[m * kD + d];
            dot *= 0.17677669529663689f;
            p[m] = dot;
            mx = fmaxf(mx, dot);
        }
        float sum = 0.f;
#pragma unroll
        for (int m = 0; m < kTok; m++) { p[m] = __expf(p[m] - mx); sum += p[m]; }
        const float inv = 1.f / sum;
        const int win = wh / kHeads, head = wh - win * kHeads;
        __half* op = g_ao + ((size_t)win * kTok + r) * kC + head * kD;
#pragma unroll 4
        for (int d = 0; d < kD; d++) {
            float a = 0.f;
#pragma unroll
            for (int m = 0; m < kTok; m++) a += p[m] * sv[m * kD + d];
            op[d] = __float2half(a * inv);
        }
    }
}

// ---------------- 3x3 conv fp16 MMA — 256 thr / 8 warps, warp = 1 row x 64 oc
// acc[2][8][4] = 64 regs/thread -> ~115 regs, 2 blocks/SM = 4 warps/SMSP.
template<int PH>
__global__ __launch_bounds__(256, 2) void conv3x3_f16_kernel(const float* __restrict__ bias,
                                                             float* __restrict__ outp) {
    constexpr int IC = (PH == 0) ? kC : kHid;
    constexpr int OC = (PH == 0) ? kHid : kC;
    constexpr int OCB = OC / 64;
    constexpr int NCH = IC / 16;
    const __half* in = (PH == 0) ? g_h0 : g_h1;
    const __half* wt = (PH == 0) ? g_wf1 : g_wf2;

    const int b = blockIdx.z;
    const int ocb = blockIdx.y;
    const int ob = ocb * 64;
    const int rt = blockIdx.x >> 1, ct = blockIdx.x & 1;
    const int r0 = rt * 8, c0col = ct * 32;

    const int tid = threadIdx.x;
    const int warp = tid >> 5, lane = tid & 31;
    const int g = lane >> 2, t = lane & 3;
    const int wm = warp;                 // 0..7, one row each

    extern __shared__ unsigned smemd[];
    const unsigned smem0 = (unsigned)__cvta_generic_to_shared(smemd);

    auto stage = [&](int ci, int bufi) {
        const unsigned sxb = smem0 + (unsigned)(bufi * 8064 * 4);
        for (int i = tid; i < 2720; i += 256) {
            int cell = i >> 3, j = i & 7;
            int y = cell / 34, x = cell - y * 34;
            int gy = r0 + y - 1, gx = c0col + x - 1;
            bool ok = (gy >= 0 && gy < kH && gx >= 0 && gx < kW);
            const __half* src = in + ((size_t)((b * kH + (ok ? gy : 0)) * kW + (ok ? gx : 0))) * IC
                                   + ci * 16 + j * 2;
            cp4(sxb + (unsigned)(((j * 10 + y) * 36 + x) << 2), src, ok ? 4 : 0);
        }
        const __half* wp = wt + (size_t)(ci * OCB + ocb) * 9216;
        const unsigned swb = sxb + 2880 * 4;
        for (int i = tid; i < 1152; i += 256) {
            int r = i >> 4, q = i & 15;
            cp16(swb + (unsigned)((r * 72 + q * 4) << 2), wp + r * 128 + q * 8);
        }
        asm volatile("cp.async.commit_group;");
    };

    float acc[2][8][4];
#pragma unroll
    for (int i = 0; i < 2; i++)
#pragma unroll
        for (int j = 0; j < 8; j++)
#pragma unroll
            for (int k = 0; k < 4; k++) acc[i][j][k] = 0.f;

    stage(0, 0);

    for (int ci = 0; ci < NCH; ci++) {
        if (ci + 1 < NCH) {
            stage(ci + 1, (ci + 1) & 1);
            asm volatile("cp.async.wait_group 1;");
        } else {
            asm volatile("cp.async.wait_group 0;");
        }
        __syncthreads();
        const unsigned* buf = smemd + (ci & 1) * 8064;
#pragma unroll
        for (int dy = 0; dy < 3; dy++) {
#pragma unroll
            for (int dx = 0; dx < 3; dx++) {
                const int tap = dy * 3 + dx;
                unsigned afr[2][4];
#pragma unroll
                for (int mf = 0; mf < 2; mf++) {
                    const int ys = wm + dy;
                    const int xb = mf * 16 + g + dx;
                    afr[mf][0] = buf[(t * 10 + ys) * 36 + xb];
                    afr[mf][1] = buf[(t * 10 + ys) * 36 + xb + 8];
                    afr[mf][2] = buf[((t + 4) * 10 + ys) * 36 + xb];
                    afr[mf][3] = buf[((t + 4) * 10 + ys) * 36 + xb + 8];
                }
                unsigned bfr[8][2];
#pragma unroll
                for (int nf = 0; nf < 8; nf++) {
                    bfr[nf][0] = buf[2880 + (t * 9 + tap) * 72 + nf * 8 + g];
                    bfr[nf][1] = buf[2880 + ((t + 4) * 9 + tap) * 72 + nf * 8 + g];
                }
#pragma unroll
                for (int mf = 0; mf < 2; mf++)
#pragma unroll
                    for (int nf = 0; nf < 8; nf++)
                        mma_f16(acc[mf][nf], afr[mf], bfr[nf]);
            }
        }
        __syncthreads();
    }

    // epilogue: warp wm owns row r0+wm; mf selects 16-px column group
#pragma unroll
    for (int mf = 0; mf < 2; mf++) {
        const int gy = r0 + wm;
        const int gxA = c0col + mf * 16 + g;
        const int gxB = gxA + 8;
        const bool okA = gxA < kW, okB = gxB < kW;
#pragma unroll
        for (int nf = 0; nf < 8; nf++) {
            const int o = ob + nf * 8 + 2 * t;
            const float bv0 = bias[o], bv1 = bias[o + 1];
            float v00 = acc[mf][nf][0] + bv0;
            float v01 = acc[mf][nf][1] + bv1;
            float v10 = acc[mf][nf][2] + bv0;
            float v11 = acc[mf][nf][3] + bv1;
            if (PH == 0) {
                if (okA) {
                    __half* op = g_h1 + ((size_t)(b * kH + gy) * kW + gxA) * kHid + o;
                    op[0] = __float2half(0.5f * v00 * (1.f + erff(v00 * 0.70710678118654752f)));
                    op[1] = __float2half(0.5f * v01 * (1.f + erff(v01 * 0.70710678118654752f)));
                }
                if (okB) {
                    __half* op = g_h1 + ((size_t)(b * kH + gy) * kW + gxB) * kHid + o;
                    op[0] = __float2half(0.5f * v10 * (1.f + erff(v10 * 0.70710678118654752f)));
                    op[1] = __float2half(0.5f * v11 * (1.f + erff(v11 * 0.70710678118654752f)));
                }
            } else {
                const size_t base0 = ((size_t)(b * OC + o) * kH + gy) * kW;
                const size_t base1 = ((size_t)(b * OC + o + 1) * kH + gy) * kW;
                if (okA) {
                    outp[base0 + gxA] = v00 + g_x1[base0 + gxA];
                    outp[base1 + gxA] = v01 + g_x1[base1 + gxA];
                }
                if (okB) {
                    outp[base0 + gxB] = v10 + g_x1[base0 + gxB];
                    outp[base1 + gxB] = v11 + g_x1[base1 + gxB];
                }
            }
        }
    }
}

// ---------------- launch -----------------------------------------------------
extern "C" void kernel_launch(void* const* d_in, const int* in_sizes, int n_in,
                              void* d_out, int out_size) {
    (void)in_sizes; (void)n_in; (void)out_size;
    const float* x       = (const float*)d_in[0];
    const float* ln1_g   = (const float*)d_in[1];
    const float* ln1_b   = (const float*)d_in[2];
    const float* qkv_w   = (const float*)d_in[3];
    const float* qkv_b   = (const float*)d_in[4];
    const float* proj_w  = (const float*)d_in[5];
    const float* proj_b  = (const float*)d_in[6];
    const float* ln2_g   = (const float*)d_in[7];
    const float* ln2_b   = (const float*)d_in[8];
    const float* conv1_w = (const float*)d_in[9];
    const float* conv1_b = (const float*)d_in[10];
    const float* conv2_w = (const float*)d_in[11];
    const float* conv2_b = (const float*)d_in[12];
    float* out = (float*)d_out;

    constexpr int kConvSmem = 2 * 8064 * 4;   // 64512 B
    static bool attr_done = false;
    if (!attr_done) {
        cudaFuncSetAttribute(conv3x3_f16_kernel<0>, cudaFuncAttributeMaxDynamicSharedMemorySize, kConvSmem);
        cudaFuncSetAttribute(conv3x3_f16_kernel<1>, cudaFuncAttributeMaxDynamicSharedMemorySize, kConvSmem);
        attr_done = true;
    }

    wprep_kernel<0><<<(1327104 + 255) / 256, 256>>>(conv1_w);
    wprep_kernel<1><<<(1327104 + 255) / 256, 256>>>(conv2_w);
    wprep_gemm_kernel<0><<<(9 * 12 * 1024 + 255) / 256, 256>>>(qkv_w);
    wprep_gemm_kernel<1><<<(3 * 12 * 1024 + 255) / 256, 256>>>(proj_w);

    ln_kernel<0><<<kNT / 256, 256>>>(x, ln1_g, ln1_b);
    gemm_f16_kernel<0><<<dim3(kNT / 256, 9), 128>>>(qkv_b, nullptr);
    attn_kernel<<<kNWin * kHeads, 64>>>();
    gemm_f16_kernel<1><<<dim3(kNT / 256, 3), 128>>>(proj_b, x);
    ln_kernel<1><<<kNT / 256, 256>>>(nullptr, ln2_g, ln2_b);
    conv3x3_f16_kernel<0><<<dim3(14, 12, kB), 256, kConvSmem>>>(conv1_b, nullptr);
    conv3x3_f16_kernel<1><<<dim3(14, 3, kB), 256, kConvSmem>>>(conv2_b, out);
}

// round 15
// speedup vs baseline: 1.0291x; 1.0291x over previous
#include <cuda_runtime.h>
#include <cuda_fp16.h>
#include <math.h>

namespace {
constexpr int kB = 32, kC = 192, kH = 56, kW = 56;
constexpr int kHeads = 6, kD = 32, kWS = 7, kShift = 3, kHid = 768;
constexpr int kNWin = kB * 8 * 8;   // 2048 windows
constexpr int kTok = kWS * kWS;     // 49
constexpr int kNT = kNWin * kTok;   // 100352 tokens
constexpr int kHWp = kH * kW;       // 3136
}

// ---------------- scratch (static __device__, allocation-free) ----------------
__device__ __half g_wf1[1327104];               // conv1 w fp16 tiles [cc][ocb][72][128]
__device__ __half g_wf2[1327104];               // conv2 w fp16 tiles
__device__ __half g_wq[3 * kC * kC];            // qkv w fp16 tiles [nb][cc][kp][128]
__device__ __half g_wp[kC * kC];                // proj w fp16 tiles
__device__ __half g_xw[(size_t)kNT * kC];       // LN1 out fp16, [win][tok][c]
__device__ __half g_q [(size_t)kNT * kC];       // q fp16 [win][head][tok][d]
__device__ __half g_kk[(size_t)kNT * kC];       // k fp16
__device__ __half g_vv[(size_t)kNT * kC];       // v fp16
__device__ __half g_ao[(size_t)kNT * kC];       // attn out fp16, [win][tok][c]
__device__ float g_x1[(size_t)kNT * kC];        // x + attn branch (NCHW)
__device__ __half g_h0[(size_t)kNT * kC];       // LN2 out, NHWC fp16
__device__ __half g_h1[(size_t)kNT * kHid];     // conv1+gelu out, NHWC fp16

// ---------------- helpers ----------------------------------------------------
__device__ __forceinline__ void mma_f16(float* d, const unsigned* a, const unsigned* b) {
    asm volatile(
        "mma.sync.aligned.m16n8k16.row.col.f32.f16.f16.f32 "
        "{%0,%1,%2,%3}, {%4,%5,%6,%7}, {%8,%9}, {%0,%1,%2,%3};\n"
        : "+f"(d[0]), "+f"(d[1]), "+f"(d[2]), "+f"(d[3])
        : "r"(a[0]), "r"(a[1]), "r"(a[2]), "r"(a[3]), "r"(b[0]), "r"(b[1]));
}
__device__ __forceinline__ void cp4(unsigned dst, const void* src, int sz) {
    asm volatile("cp.async.ca.shared.global [%0], [%1], 4, %2;" :: "r"(dst), "l"(src), "r"(sz));
}
__device__ __forceinline__ void cp16(unsigned dst, const void* src) {
    asm volatile("cp.async.cg.shared.global [%0], [%1], 16;" :: "r"(dst), "l"(src));
}

// ---------------- conv weight prep (unchanged) --------------------------------
template<int PH>
__global__ void wprep_kernel(const float* __restrict__ w) {
    constexpr int IC = (PH == 0) ? kC : kHid;
    constexpr int OC = (PH == 0) ? kHid : kC;
    constexpr int OCB = OC / 64;
    constexpr int TOT = (IC / 16) * OCB * 9216;
    __half* dst = (PH == 0) ? g_wf1 : g_wf2;
    int i = blockIdx.x * 256 + threadIdx.x;
    if (i >= TOT) return;
    int blk = i / 9216, rem = i - blk * 9216;
    int cc = blk / OCB, ocb = blk - cc * OCB;
    int row = rem >> 7, e = rem & 127;
    int kp = row / 9, tap = row - kp * 9;
    int n = e >> 1, lo = e & 1;
    int o = ocb * 64 + n, ic = cc * 16 + kp * 2 + lo;
    dst[i] = __float2half(w[((size_t)o * IC + ic) * 9 + tap]);
}

// ---------------- gemm weight prep (unchanged) --------------------------------
template<int P>
__global__ void wprep_gemm_kernel(const float* __restrict__ w) {
    constexpr int NB = (P == 0) ? 9 : 3;
    constexpr int TOT = NB * 12 * 1024;
    __half* dst = (P == 0) ? g_wq : g_wp;
    int i = blockIdx.x * 256 + threadIdx.x;
    if (i >= TOT) return;
    int blk = i >> 10, rem = i & 1023;
    int nb = blk / 12, cc = blk - nb * 12;
    int kp = rem >> 7, e = rem & 127;
    int n = e >> 1, lo = e & 1;
    dst[i] = __float2half(w[(size_t)(nb * 64 + n) * kC + cc * 16 + kp * 2 + lo]);
}

// ---------------- LayerNorm (unchanged) ---------------------------------------
template<int MODE>
__global__ void ln_kernel(const float* __restrict__ xin,
                          const float* __restrict__ gam,
                          const float* __restrict__ bet) {
    int p = blockIdx.x * 256 + threadIdx.x;
    if (p >= kNT) return;
    const float* src = (MODE == 0) ? xin : g_x1;
    int b = p / kHWp;
    int rem = p - b * kHWp;
    int hp = rem / kW, wp = rem - (rem / kW) * kW;
    int h = hp, w = wp;
    if (MODE == 0) {
        h = hp + kShift; if (h >= kH) h -= kH;
        w = wp + kShift; if (w >= kW) w -= kW;
    }
    const float* xp = src + ((size_t)b * kC) * kHWp + h * kW + w;
    float s = 0.f, s2 = 0.f;
#pragma unroll 4
    for (int c = 0; c < kC; c++) { float v = xp[(size_t)c * kHWp]; s += v; s2 += v * v; }
    float m = s * (1.f / kC);
    float var = s2 * (1.f / kC) - m * m;
    float rs = rsqrtf(var + 1e-5f);
    if (MODE == 0) {
        int win = b * 64 + (hp / 7) * 8 + (wp / 7);
        int tok = (hp % 7) * 7 + (wp % 7);
        __half* op = g_xw + ((size_t)win * kTok + tok) * kC;
#pragma unroll 4
        for (int c = 0; c < kC; c++) {
            float v = (xp[(size_t)c * kHWp] - m) * rs * gam[c] + bet[c];
            op[c] = __float2half(v);
        }
    } else {
        __half* op = g_h0 + ((size_t)(b * kH + h) * kW + w) * kC;
#pragma unroll 4
        for (int c = 0; c < kC; c++) {
            float v = (xp[(size_t)c * kHWp] - m) * rs * gam[c] + bet[c];
            op[c] = __float2half(v);
        }
    }
}

// ---------------- GEMM fp16 m16n8k16 + cp.async double buffer (R13 winner) ---
template<int EPI>
__global__ __launch_bounds__(128, 2) void gemm_f16_kernel(const float* __restrict__ bias,
                                                          const float* __restrict__ xin) {
    __shared__ unsigned gsm[2 * 3648];
    const __half* A = (EPI == 0) ? g_xw : g_ao;
    const __half* Wg = (EPI == 0) ? g_wq : g_wp;
    const int tid = threadIdx.x;
    const int warp = tid >> 5, lane = tid & 31;
    const int g = lane >> 2, t = lane & 3;
    const int wm = warp;
    const int tokbase = blockIdx.x * 256;
    const int nb = blockIdx.y;
    const int ob = nb * 64;
    const unsigned smem0 = (unsigned)__cvta_generic_to_shared(gsm);

    const int atok = tid >> 1, ahalf = tid & 1;
    const int wrow = tid >> 4, wq = tid & 15;

    auto stage = [&](int cc, int bufi) {
        const unsigned base = smem0 + (unsigned)(bufi * 3648 * 4);
#pragma unroll
        for (int s = 0; s < 4; s++) {
            const int tok = s * 64 + atok;
            cp16(base + (unsigned)((tok * 12 + ahalf * 4) << 2),
                 A + (size_t)(tokbase + tok) * kC + cc * 16 + ahalf * 8);
        }
        cp16(base + (unsigned)((3072 + wrow * 72 + wq * 4) << 2),
             Wg + (size_t)(nb * 12 + cc) * 1024 + wrow * 128 + wq * 8);
        asm volatile("cp.async.commit_group;");
    };

    float acc[4][8][4];
#pragma unroll
    for (int i = 0; i < 4; i++)
#pragma unroll
        for (int j = 0; j < 8; j++)
#pragma unroll
            for (int k = 0; k < 4; k++) acc[i][j][k] = 0.f;

    stage(0, 0);

    for (int cc = 0; cc < 12; cc++) {
        if (cc + 1 < 12) {
            stage(cc + 1, (cc + 1) & 1);
            asm volatile("cp.async.wait_group 1;");
        } else {
            asm volatile("cp.async.wait_group 0;");
        }
        __syncthreads();
        const unsigned* buf = gsm + (cc & 1) * 3648;
        unsigned afr[4][4];
#pragma unroll
        for (int mf = 0; mf < 4; mf++) {
            const int r0 = (wm * 64 + mf * 16 + g) * 12;
            afr[mf][0] = buf[r0 + t];
            afr[mf][1] = buf[r0 + 96 + t];
            afr[mf][2] = buf[r0 + t + 4];
            afr[mf][3] = buf[r0 + 96 + t + 4];
        }
        unsigned bfr[8][2];
#pragma unroll
        for (int nf = 0; nf < 8; nf++) {
            bfr[nf][0] = buf[3072 + t * 72 + nf * 8 + g];
            bfr[nf][1] = buf[3072 + (t + 4) * 72 + nf * 8 + g];
        }
#pragma unroll
        for (int mf = 0; mf < 4; mf++)
#pragma unroll
            for (int nf = 0; nf < 8; nf++)
                mma_f16(acc[mf][nf], afr[mf], bfr[nf]);
        __syncthreads();
    }

#pragma unroll
    for (int mf = 0; mf < 4; mf++) {
        const int tk0 = tokbase + wm * 64 + mf * 16 + g;
#pragma unroll
        for (int nf = 0; nf < 8; nf++) {
            const int o0 = ob + nf * 8 + 2 * t;
            const float bv0 = bias[o0], bv1 = bias[o0 + 1];
            float vals[4] = {acc[mf][nf][0] + bv0, acc[mf][nf][1] + bv1,
                             acc[mf][nf][2] + bv0, acc[mf][nf][3] + bv1};
#pragma unroll
            for (int q = 0; q < 4; q++) {
                const int n_tok = tk0 + (q >> 1) * 8;
                const int mo = o0 + (q & 1);
                const int win = n_tok / 49, tok = n_tok - win * 49;
                if (EPI == 0) {
                    int sec = mo / kC;
                    int c = mo - sec * kC;
                    __half* dst = (sec == 0) ? g_q : (sec == 1) ? g_kk : g_vv;
                    dst[((size_t)(win * kHeads + (c >> 5)) * kTok + tok) * kD + (c & 31)] =
                        __float2half(vals[q]);
                } else {
                    int bb  = win >> 6;
                    int whh = (win >> 3) & 7;
                    int www = win & 7;
                    int ti = tok / 7, tj = tok - ti * 7;
                    int hi = whh * 7 + ti + kShift; if (hi >= kH) hi -= kH;
                    int wi = www * 7 + tj + kShift; if (wi >= kW) wi -= kW;
                    size_t idx = ((size_t)(bb * kC + mo) * kH + hi) * kW + wi;
                    g_x1[idx] = xin[idx] + vals[q];
                }
            }
        }
    }
}

// ---------------- attention: fp16 q/k/v in gmem, fp32 compute ----------------
__global__ __launch_bounds__(64) void attn_kernel() {
    const int wh = blockIdx.x;
    __shared__ float sq[kTok * 33], sk[kTok * kD], sv[kTok * kD];
    const size_t base = (size_t)wh * kTok * kD;
    for (int i = threadIdx.x; i < kTok * kD; i += 64) {
        int r = i >> 5, d = i & 31;
        sq[r * 33 + d] = __half2float(g_q[base + i]);
        sk[i] = __half2float(g_kk[base + i]);
        sv[i] = __half2float(g_vv[base + i]);
    }
    __syncthreads();
    const int r = threadIdx.x;
    if (r < kTok) {
        float qr[kD];
#pragma unroll
        for (int d = 0; d < kD; d++) qr[d] = sq[r * 33 + d];
        float p[kTok];
        float mx = -1e30f;
#pragma unroll
        for (int m = 0; m < kTok; m++) {
            float dot = 0.f;
#pragma unroll
            for (int d = 0; d < kD; d++) dot += qr[d] * sk[m * kD + d];
            dot *= 0.17677669529663689f;
            p[m] = dot;
            mx = fmaxf(mx, dot);
        }
        float sum = 0.f;
#pragma unroll
        for (int m = 0; m < kTok; m++) { p[m] = __expf(p[m] - mx); sum += p[m]; }
        const float inv = 1.f / sum;
        const int win = wh / kHeads, head = wh - win * kHeads;
        __half* op = g_ao + ((size_t)win * kTok + r) * kC + head * kD;
#pragma unroll 4
        for (int d = 0; d < kD; d++) {
            float a = 0.f;
#pragma unroll
            for (int m = 0; m < kTok; m++) a += p[m] * sv[m * kD + d];
            op[d] = __float2half(a * inv);
        }
    }
}

// ---------------- 3x3 conv fp16 MMA (exact R13 winner) -----------------------
template<int PH>
__global__ __launch_bounds__(128, 2) void conv3x3_f16_kernel(const float* __restrict__ bias,
                                                             float* __restrict__ outp) {
    constexpr int IC = (PH == 0) ? kC : kHid;
    constexpr int OC = (PH == 0) ? kHid : kC;
    constexpr int OCB = OC / 64;
    constexpr int NCH = IC / 16;
    const __half* in = (PH == 0) ? g_h0 : g_h1;
    const __half* wt = (PH == 0) ? g_wf1 : g_wf2;

    const int b = blockIdx.z;
    const int ocb = blockIdx.y;
    const int ob = ocb * 64;
    const int rt = blockIdx.x >> 1, ct = blockIdx.x & 1;
    const int r0 = rt * 8, c0col = ct * 32;

    const int tid = threadIdx.x;
    const int warp = tid >> 5, lane = tid & 31;
    const int g = lane >> 2, t = lane & 3;
    const int wm = warp;

    extern __shared__ unsigned smemd[];
    const unsigned smem0 = (unsigned)__cvta_generic_to_shared(smemd);

    auto stage = [&](int ci, int bufi) {
        const unsigned sxb = smem0 + (unsigned)(bufi * 8064 * 4);
        for (int i = tid; i < 2720; i += 128) {
            int cell = i >> 3, j = i & 7;
            int y = cell / 34, x = cell - y * 34;
            int gy = r0 + y - 1, gx = c0col + x - 1;
            bool ok = (gy >= 0 && gy < kH && gx >= 0 && gx < kW);
            const __half* src = in + ((size_t)((b * kH + (ok ? gy : 0)) * kW + (ok ? gx : 0))) * IC
                                   + ci * 16 + j * 2;
            cp4(sxb + (unsigned)(((j * 10 + y) * 36 + x) << 2), src, ok ? 4 : 0);
        }
        const __half* wp = wt + (size_t)(ci * OCB + ocb) * 9216;
        const unsigned swb = sxb + 2880 * 4;
        for (int i = tid; i < 1152; i += 128) {
            int r = i >> 4, q = i & 15;
            cp16(swb + (unsigned)((r * 72 + q * 4) << 2), wp + r * 128 + q * 8);
        }
        asm volatile("cp.async.commit_group;");
    };

    float acc[4][8][4];
#pragma unroll
    for (int i = 0; i < 4; i++)
#pragma unroll
        for (int j = 0; j < 8; j++)
#pragma unroll
            for (int k = 0; k < 4; k++) acc[i][j][k] = 0.f;

    stage(0, 0);

    for (int ci = 0; ci < NCH; ci++) {
        if (ci + 1 < NCH) {
            stage(ci + 1, (ci + 1) & 1);
            asm volatile("cp.async.wait_group 1;");
        } else {
            asm volatile("cp.async.wait_group 0;");
        }
        __syncthreads();
        const unsigned* buf = smemd + (ci & 1) * 8064;
#pragma unroll
        for (int dy = 0; dy < 3; dy++) {
#pragma unroll
            for (int dx = 0; dx < 3; dx++) {
                const int tap = dy * 3 + dx;
                unsigned afr[4][4];
#pragma unroll
                for (int mf = 0; mf < 4; mf++) {
                    const int ys = wm * 2 + (mf >> 1) + dy;
                    const int xb = (mf & 1) * 16 + g + dx;
                    afr[mf][0] = buf[(t * 10 + ys) * 36 + xb];
                    afr[mf][1] = buf[(t * 10 + ys) * 36 + xb + 8];
                    afr[mf][2] = buf[((t + 4) * 10 + ys) * 36 + xb];
                    afr[mf][3] = buf[((t + 4) * 10 + ys) * 36 + xb + 8];
                }
                unsigned bfr[8][2];
#pragma unroll
                for (int nf = 0; nf < 8; nf++) {
                    bfr[nf][0] = buf[2880 + (t * 9 + tap) * 72 + nf * 8 + g];
                    bfr[nf][1] = buf[2880 + ((t + 4) * 9 + tap) * 72 + nf * 8 + g];
                }
#pragma unroll
                for (int mf = 0; mf < 4; mf++)
#pragma unroll
                    for (int nf = 0; nf < 8; nf++)
                        mma_f16(acc[mf][nf], afr[mf], bfr[nf]);
            }
        }
        __syncthreads();
    }

#pragma unroll
    for (int mf = 0; mf < 4; mf++) {
        const int gy = r0 + wm * 2 + (mf >> 1);
        const int gxA = c0col + (mf & 1) * 16 + g;
        const int gxB = gxA + 8;
        const bool okA = gxA < kW, okB = gxB < kW;
#pragma unroll
        for (int nf = 0; nf < 8; nf++) {
            const int o = ob + nf * 8 + 2 * t;
            const float bv0 = bias[o], bv1 = bias[o + 1];
            float v00 = acc[mf][nf][0] + bv0;
            float v01 = acc[mf][nf][1] + bv1;
            float v10 = acc[mf][nf][2] + bv0;
            float v11 = acc[mf][nf][3] + bv1;
            if (PH == 0) {
                if (okA) {
                    __half* op = g_h1 + ((size_t)(b * kH + gy) * kW + gxA) * kHid + o;
                    op[0] = __float2half(0.5f * v00 * (1.f + erff(v00 * 0.70710678118654752f)));
                    op[1] = __float2half(0.5f * v01 * (1.f + erff(v01 * 0.70710678118654752f)));
                }
                if (okB) {
                    __half* op = g_h1 + ((size_t)(b * kH + gy) * kW + gxB) * kHid + o;
                    op[0] = __float2half(0.5f * v10 * (1.f + erff(v10 * 0.70710678118654752f)));
                    op[1] = __float2half(0.5f * v11 * (1.f + erff(v11 * 0.70710678118654752f)));
                }
            } else {
                const size_t base0 = ((size_t)(b * OC + o) * kH + gy) * kW;
                const size_t base1 = ((size_t)(b * OC + o + 1) * kH + gy) * kW;
                if (okA) {
                    outp[base0 + gxA] = v00 + g_x1[base0 + gxA];
                    outp[base1 + gxA] = v01 + g_x1[base1 + gxA];
                }
                if (okB) {
                    outp[base0 + gxB] = v10 + g_x1[base0 + gxB];
                    outp[base1 + gxB] = v11 + g_x1[base1 + gxB];
                }
            }
        }
    }
}

// ---------------- launch -----------------------------------------------------
extern "C" void kernel_launch(void* const* d_in, const int* in_sizes, int n_in,
                              void* d_out, int out_size) {
    (void)in_sizes; (void)n_in; (void)out_size;
    const float* x       = (const float*)d_in[0];
    const float* ln1_g   = (const float*)d_in[1];
    const float* ln1_b   = (const float*)d_in[2];
    const float* qkv_w   = (const float*)d_in[3];
    const float* qkv_b   = (const float*)d_in[4];
    const float* proj_w  = (const float*)d_in[5];
    const float* proj_b  = (const float*)d_in[6];
    const float* ln2_g   = (const float*)d_in[7];
    const float* ln2_b   = (const float*)d_in[8];
    const float* conv1_w = (const float*)d_in[9];
    const float* conv1_b = (const float*)d_in[10];
    const float* conv2_w = (const float*)d_in[11];
    const float* conv2_b = (const float*)d_in[12];
    float* out = (float*)d_out;

    constexpr int kConvSmem = 2 * 8064 * 4;   // 64512 B
    static bool attr_done = false;
    if (!attr_done) {
        cudaFuncSetAttribute(conv3x3_f16_kernel<0>, cudaFuncAttributeMaxDynamicSharedMemorySize, kConvSmem);
        cudaFuncSetAttribute(conv3x3_f16_kernel<1>, cudaFuncAttributeMaxDynamicSharedMemorySize, kConvSmem);
        attr_done = true;
    }

    wprep_kernel<0><<<(1327104 + 255) / 256, 256>>>(conv1_w);
    wprep_kernel<1><<<(1327104 + 255) / 256, 256>>>(conv2_w);
    wprep_gemm_kernel<0><<<(9 * 12 * 1024 + 255) / 256, 256>>>(qkv_w);
    wprep_gemm_kernel<1><<<(3 * 12 * 1024 + 255) / 256, 256>>>(proj_w);

    ln_kernel<0><<<kNT / 256, 256>>>(x, ln1_g, ln1_b);
    gemm_f16_kernel<0><<<dim3(kNT / 256, 9), 128>>>(qkv_b, nullptr);
    attn_kernel<<<kNWin * kHeads, 64>>>();
    gemm_f16_kernel<1><<<dim3(kNT / 256, 3), 128>>>(proj_b, x);
    ln_kernel<1><<<kNT / 256, 256>>>(nullptr, ln2_g, ln2_b);
    conv3x3_f16_kernel<0><<<dim3(14, 12, kB), 128, kConvSmem>>>(conv1_b, nullptr);
    conv3x3_f16_kernel<1><<<dim3(14, 3, kB), 128, kConvSmem>>>(conv2_b, out);
}

// round 17
// speedup vs baseline: 1.0876x; 1.0568x over previous
#include <cuda_runtime.h>
#include <cuda_fp16.h>
#include <math.h>

namespace {
constexpr int kB = 32, kC = 192, kH = 56, kW = 56;
constexpr int kHeads = 6, kD = 32, kWS = 7, kShift = 3, kHid = 768;
constexpr int kNWin = kB * 8 * 8;   // 2048 windows
constexpr int kTok = kWS * kWS;     // 49
constexpr int kNT = kNWin * kTok;   // 100352 tokens
constexpr int kHWp = kH * kW;       // 3136
}

// ---------------- scratch (static __device__, allocation-free) ----------------
__device__ __half g_wf1[1327104];               // conv1 w fp16 tiles [cc][ocb][72][128]
__device__ __half g_wf2[1327104];               // conv2 w fp16 tiles
__device__ __half g_wq[3 * kC * kC];            // qkv w fp16 tiles [nb][cc][kp][128]
__device__ __half g_wp[kC * kC];                // proj w fp16 tiles
__device__ __half g_xw[(size_t)kNT * kC];       // LN1 out fp16, [win][tok][c]
__device__ __half g_q [(size_t)kNT * kC];       // q fp16 [win][head][tok][d]
__device__ __half g_kk[(size_t)kNT * kC];       // k fp16
__device__ __half g_vv[(size_t)kNT * kC];       // v fp16
__device__ __half g_ao[(size_t)kNT * kC];       // attn out fp16, [win][tok][c]
__device__ float g_x1[(size_t)kNT * kC];        // x + attn branch (NCHW)
__device__ __half g_h0[(size_t)kNT * kC];       // LN2 out, NHWC fp16
__device__ __half g_h1[(size_t)kNT * kHid];     // conv1+gelu out, NHWC fp16

// ---------------- helpers ----------------------------------------------------
__device__ __forceinline__ void mma_f16(float* d, const unsigned* a, const unsigned* b) {
    asm volatile(
        "mma.sync.aligned.m16n8k16.row.col.f32.f16.f16.f32 "
        "{%0,%1,%2,%3}, {%4,%5,%6,%7}, {%8,%9}, {%0,%1,%2,%3};\n"
        : "+f"(d[0]), "+f"(d[1]), "+f"(d[2]), "+f"(d[3])
        : "r"(a[0]), "r"(a[1]), "r"(a[2]), "r"(a[3]), "r"(b[0]), "r"(b[1]));
}
__device__ __forceinline__ void cp4(unsigned dst, const void* src, int sz) {
    asm volatile("cp.async.ca.shared.global [%0], [%1], 4, %2;" :: "r"(dst), "l"(src), "r"(sz));
}
__device__ __forceinline__ void cp16(unsigned dst, const void* src) {
    asm volatile("cp.async.cg.shared.global [%0], [%1], 16;" :: "r"(dst), "l"(src));
}
// packed f32x2
typedef unsigned long long ull;
__device__ __forceinline__ ull pk2(float lo, float hi) {
    ull r; asm("mov.b64 %0, {%1, %2};" : "=l"(r) : "f"(lo), "f"(hi)); return r;
}
__device__ __forceinline__ void upk2(ull v, float& lo, float& hi) {
    asm("mov.b64 {%0, %1}, %2;" : "=f"(lo), "=f"(hi) : "l"(v));
}
__device__ __forceinline__ ull fma2(ull a, ull b, ull c) {
    ull r; asm("fma.rn.f32x2 %0, %1, %2, %3;" : "=l"(r) : "l"(a), "l"(b), "l"(c)); return r;
}
__device__ __forceinline__ void lds2u64(ull& a, ull& b, unsigned saddr) {
    asm volatile("ld.shared.v2.u64 {%0, %1}, [%2];" : "=l"(a), "=l"(b) : "r"(saddr));
}

// ---------------- conv weight prep (unchanged) --------------------------------
template<int PH>
__global__ void wprep_kernel(const float* __restrict__ w) {
    constexpr int IC = (PH == 0) ? kC : kHid;
    constexpr int OC = (PH == 0) ? kHid : kC;
    constexpr int OCB = OC / 64;
    constexpr int TOT = (IC / 16) * OCB * 9216;
    __half* dst = (PH == 0) ? g_wf1 : g_wf2;
    int i = blockIdx.x * 256 + threadIdx.x;
    if (i >= TOT) return;
    int blk = i / 9216, rem = i - blk * 9216;
    int cc = blk / OCB, ocb = blk - cc * OCB;
    int row = rem >> 7, e = rem & 127;
    int kp = row / 9, tap = row - kp * 9;
    int n = e >> 1, lo = e & 1;
    int o = ocb * 64 + n, ic = cc * 16 + kp * 2 + lo;
    dst[i] = __float2half(w[((size_t)o * IC + ic) * 9 + tap]);
}

// ---------------- gemm weight prep (unchanged) --------------------------------
template<int P>
__global__ void wprep_gemm_kernel(const float* __restrict__ w) {
    constexpr int NB = (P == 0) ? 9 : 3;
    constexpr int TOT = NB * 12 * 1024;
    __half* dst = (P == 0) ? g_wq : g_wp;
    int i = blockIdx.x * 256 + threadIdx.x;
    if (i >= TOT) return;
    int blk = i >> 10, rem = i & 1023;
    int nb = blk / 12, cc = blk - nb * 12;
    int kp = rem >> 7, e = rem & 127;
    int n = e >> 1, lo = e & 1;
    dst[i] = __float2half(w[(size_t)(nb * 64 + n) * kC + cc * 16 + kp * 2 + lo]);
}

// ---------------- LayerNorm (unchanged) ---------------------------------------
template<int MODE>
__global__ void ln_kernel(const float* __restrict__ xin,
                          const float* __restrict__ gam,
                          const float* __restrict__ bet) {
    int p = blockIdx.x * 256 + threadIdx.x;
    if (p >= kNT) return;
    const float* src = (MODE == 0) ? xin : g_x1;
    int b = p / kHWp;
    int rem = p - b * kHWp;
    int hp = rem / kW, wp = rem - (rem / kW) * kW;
    int h = hp, w = wp;
    if (MODE == 0) {
        h = hp + kShift; if (h >= kH) h -= kH;
        w = wp + kShift; if (w >= kW) w -= kW;
    }
    const float* xp = src + ((size_t)b * kC) * kHWp + h * kW + w;
    float s = 0.f, s2 = 0.f;
#pragma unroll 4
    for (int c = 0; c < kC; c++) { float v = xp[(size_t)c * kHWp]; s += v; s2 += v * v; }
    float m = s * (1.f / kC);
    float var = s2 * (1.f / kC) - m * m;
    float rs = rsqrtf(var + 1e-5f);
    if (MODE == 0) {
        int win = b * 64 + (hp / 7) * 8 + (wp / 7);
        int tok = (hp % 7) * 7 + (wp % 7);
        __half* op = g_xw + ((size_t)win * kTok + tok) * kC;
#pragma unroll 4
        for (int c = 0; c < kC; c++) {
            float v = (xp[(size_t)c * kHWp] - m) * rs * gam[c] + bet[c];
            op[c] = __float2half(v);
        }
    } else {
        __half* op = g_h0 + ((size_t)(b * kH + h) * kW + w) * kC;
#pragma unroll 4
        for (int c = 0; c < kC; c++) {
            float v = (xp[(size_t)c * kHWp] - m) * rs * gam[c] + bet[c];
            op[c] = __float2half(v);
        }
    }
}

// ---------------- GEMM fp16 m16n8k16 + cp.async double buffer ----------------
template<int EPI>
__global__ __launch_bounds__(128, 2) void gemm_f16_kernel(const float* __restrict__ bias,
                                                          const float* __restrict__ xin) {
    __shared__ unsigned gsm[2 * 3648];
    const __half* A = (EPI == 0) ? g_xw : g_ao;
    const __half* Wg = (EPI == 0) ? g_wq : g_wp;
    const int tid = threadIdx.x;
    const int warp = tid >> 5, lane = tid & 31;
    const int g = lane >> 2, t = lane & 3;
    const int wm = warp;
    const int tokbase = blockIdx.x * 256;
    const int nb = blockIdx.y;
    const int ob = nb * 64;
    const unsigned smem0 = (unsigned)__cvta_generic_to_shared(gsm);

    const int atok = tid >> 1, ahalf = tid & 1;
    const int wrow = tid >> 4, wq = tid & 15;

    auto stage = [&](int cc, int bufi) {
        const unsigned base = smem0 + (unsigned)(bufi * 3648 * 4);
#pragma unroll
        for (int s = 0; s < 4; s++) {
            const int tok = s * 64 + atok;
            cp16(base + (unsigned)((tok * 12 + ahalf * 4) << 2),
                 A + (size_t)(tokbase + tok) * kC + cc * 16 + ahalf * 8);
        }
        cp16(base + (unsigned)((3072 + wrow * 72 + wq * 4) << 2),
             Wg + (size_t)(nb * 12 + cc) * 1024 + wrow * 128 + wq * 8);
        asm volatile("cp.async.commit_group;");
    };

    float acc[4][8][4];
#pragma unroll
    for (int i = 0; i < 4; i++)
#pragma unroll
        for (int j = 0; j < 8; j++)
#pragma unroll
            for (int k = 0; k < 4; k++) acc[i][j][k] = 0.f;

    stage(0, 0);

    for (int cc = 0; cc < 12; cc++) {
        if (cc + 1 < 12) {
            stage(cc + 1, (cc + 1) & 1);
            asm volatile("cp.async.wait_group 1;");
        } else {
            asm volatile("cp.async.wait_group 0;");
        }
        __syncthreads();
        const unsigned* buf = gsm + (cc & 1) * 3648;
        unsigned afr[4][4];
#pragma unroll
        for (int mf = 0; mf < 4; mf++) {
            const int r0 = (wm * 64 + mf * 16 + g) * 12;
            afr[mf][0] = buf[r0 + t];
            afr[mf][1] = buf[r0 + 96 + t];
            afr[mf][2] = buf[r0 + t + 4];
            afr[mf][3] = buf[r0 + 96 + t + 4];
        }
        unsigned bfr[8][2];
#pragma unroll
        for (int nf = 0; nf < 8; nf++) {
            bfr[nf][0] = buf[3072 + t * 72 + nf * 8 + g];
            bfr[nf][1] = buf[3072 + (t + 4) * 72 + nf * 8 + g];
        }
#pragma unroll
        for (int mf = 0; mf < 4; mf++)
#pragma unroll
            for (int nf = 0; nf < 8; nf++)
                mma_f16(acc[mf][nf], afr[mf], bfr[nf]);
        __syncthreads();
    }

#pragma unroll
    for (int mf = 0; mf < 4; mf++) {
        const int tk0 = tokbase + wm * 64 + mf * 16 + g;
#pragma unroll
        for (int nf = 0; nf < 8; nf++) {
            const int o0 = ob + nf * 8 + 2 * t;
            const float bv0 = bias[o0], bv1 = bias[o0 + 1];
            float vals[4] = {acc[mf][nf][0] + bv0, acc[mf][nf][1] + bv1,
                             acc[mf][nf][2] + bv0, acc[mf][nf][3] + bv1};
#pragma unroll
            for (int qq = 0; qq < 2; qq++) {
                const int n_tok = tk0 + qq * 8;
                const int win = n_tok / 49, tok = n_tok - win * 49;
                if (EPI == 0) {
                    // o0, o0+1 are contiguous d-indices within one head -> half2 store
                    const int sec = o0 / kC;
                    const int c = o0 - sec * kC;
                    __half* dst = (sec == 0) ? g_q : (sec == 1) ? g_kk : g_vv;
                    __half2 hv = __floats2half2_rn(vals[qq * 2], vals[qq * 2 + 1]);
                    *(__half2*)&dst[((size_t)(win * kHeads + (c >> 5)) * kTok + tok) * kD + (c & 31)] = hv;
                } else {
#pragma unroll
                    for (int e = 0; e < 2; e++) {
                        const int mo = o0 + e;
                        int bb  = win >> 6;
                        int whh = (win >> 3) & 7;
                        int www = win & 7;
                        int ti = tok / 7, tj = tok - ti * 7;
                        int hi = whh * 7 + ti + kShift; if (hi >= kH) hi -= kH;
                        int wi = www * 7 + tj + kShift; if (wi >= kW) wi -= kW;
                        size_t idx = ((size_t)(bb * kC + mo) * kH + hi) * kW + wi;
                        g_x1[idx] = xin[idx] + vals[qq * 2 + e];
                    }
                }
            }
        }
    }
}

// ---------------- attention: packed f32x2 math, fp16 q/k/v -------------------
__global__ __launch_bounds__(64) void attn_kernel() {
    const int wh = blockIdx.x;
    __shared__ float sk[kTok * kD], sv[kTok * kD];
    const size_t base = (size_t)wh * kTok * kD;
    for (int i = threadIdx.x; i < kTok * kD; i += 64) {
        sk[i] = __half2float(g_kk[base + i]);
        sv[i] = __half2float(g_vv[base + i]);
    }
    __syncthreads();
    const unsigned skb = (unsigned)__cvta_generic_to_shared(sk);
    const unsigned svb = (unsigned)__cvta_generic_to_shared(sv);
    const int r = threadIdx.x;
    if (r < kTok) {
        // q row -> packed f32x2 regs (4x LDG.128 of fp16)
        ull qr2[16];
        {
            const uint4* qp = (const uint4*)(g_q + base + r * kD);
#pragma unroll
            for (int v = 0; v < 4; v++) {
                uint4 u = qp[v];
                const unsigned uu[4] = {u.x, u.y, u.z, u.w};
#pragma unroll
                for (int j = 0; j < 4; j++) {
                    float2 f = __half22float2(*(const __half2*)&uu[j]);
                    qr2[v * 4 + j] = pk2(f.x, f.y);
                }
            }
        }
        float p[kTok];
        float mx = -1e30f;
#pragma unroll 4
        for (int m = 0; m < kTok; m++) {
            ull a0 = pk2(0.f, 0.f), a1 = pk2(0.f, 0.f);
            const unsigned rb = skb + m * 128;
#pragma unroll
            for (int j = 0; j < 8; j++) {
                ull x, y;
                lds2u64(x, y, rb + j * 16);
                a0 = fma2(qr2[2 * j], x, a0);
                a1 = fma2(qr2[2 * j + 1], y, a1);
            }
            float l0, h0, l1, h1;
            upk2(a0, l0, h0); upk2(a1, l1, h1);
            float dot = ((l0 + h0) + (l1 + h1)) * 0.17677669529663689f;
            p[m] = dot;
            mx = fmaxf(mx, dot);
        }
        float sum = 0.f;
#pragma unroll
        for (int m = 0; m < kTok; m++) { p[m] = __expf(p[m] - mx); sum += p[m]; }
        const float inv = 1.f / sum;

        ull acc2[16];
#pragma unroll
        for (int j = 0; j < 16; j++) acc2[j] = pk2(0.f, 0.f);
#pragma unroll 4
        for (int m = 0; m < kTok; m++) {
            const ull pm2 = pk2(p[m], p[m]);
            const unsigned rb = svb + m * 128;
#pragma unroll
            for (int j = 0; j < 8; j++) {
                ull x, y;
                lds2u64(x, y, rb + j * 16);
                acc2[2 * j]     = fma2(pm2, x, acc2[2 * j]);
                acc2[2 * j + 1] = fma2(pm2, y, acc2[2 * j + 1]);
            }
        }
        const int win = wh / kHeads, head = wh - win * kHeads;
        __half2* op = (__half2*)(g_ao + ((size_t)win * kTok + r) * kC + head * kD);
#pragma unroll
        for (int j = 0; j < 16; j++) {
            float lo, hi;
            upk2(acc2[j], lo, hi);
            op[j] = __floats2half2_rn(lo * inv, hi * inv);
        }
    }
}

// ---------------- 3x3 conv fp16 MMA (exact R13 winner) -----------------------
template<int PH>
__global__ __launch_bounds__(128, 2) void conv3x3_f16_kernel(const float* __restrict__ bias,
                                                             float* __restrict__ outp) {
    constexpr int IC = (PH == 0) ? kC : kHid;
    constexpr int OC = (PH == 0) ? kHid : kC;
    constexpr int OCB = OC / 64;
    constexpr int NCH = IC / 16;
    const __half* in = (PH == 0) ? g_h0 : g_h1;
    const __half* wt = (PH == 0) ? g_wf1 : g_wf2;

    const int b = blockIdx.z;
    const int ocb = blockIdx.y;
    const int ob = ocb * 64;
    const int rt = blockIdx.x >> 1, ct = blockIdx.x & 1;
    const int r0 = rt * 8, c0col = ct * 32;

    const int tid = threadIdx.x;
    const int warp = tid >> 5, lane = tid & 31;
    const int g = lane >> 2, t = lane & 3;
    const int wm = warp;

    extern __shared__ unsigned smemd[];
    const unsigned smem0 = (unsigned)__cvta_generic_to_shared(smemd);

    auto stage = [&](int ci, int bufi) {
        const unsigned sxb = smem0 + (unsigned)(bufi * 8064 * 4);
        for (int i = tid; i < 2720; i += 128) {
            int cell = i >> 3, j = i & 7;
            int y = cell / 34, x = cell - y * 34;
            int gy = r0 + y - 1, gx = c0col + x - 1;
            bool ok = (gy >= 0 && gy < kH && gx >= 0 && gx < kW);
            const __half* src = in + ((size_t)((b * kH + (ok ? gy : 0)) * kW + (ok ? gx : 0))) * IC
                                   + ci * 16 + j * 2;
            cp4(sxb + (unsigned)(((j * 10 + y) * 36 + x) << 2), src, ok ? 4 : 0);
        }
        const __half* wp = wt + (size_t)(ci * OCB + ocb) * 9216;
        const unsigned swb = sxb + 2880 * 4;
        for (int i = tid; i < 1152; i += 128) {
            int r = i >> 4, q = i & 15;
            cp16(swb + (unsigned)((r * 72 + q * 4) << 2), wp + r * 128 + q * 8);
        }
        asm volatile("cp.async.commit_group;");
    };

    float acc[4][8][4];
#pragma unroll
    for (int i = 0; i < 4; i++)
#pragma unroll
        for (int j = 0; j < 8; j++)
#pragma unroll
            for (int k = 0; k < 4; k++) acc[i][j][k] = 0.f;

    stage(0, 0);

    for (int ci = 0; ci < NCH; ci++) {
        if (ci + 1 < NCH) {
            stage(ci + 1, (ci + 1) & 1);
            asm volatile("cp.async.wait_group 1;");
        } else {
            asm volatile("cp.async.wait_group 0;");
        }
        __syncthreads();
        const unsigned* buf = smemd + (ci & 1) * 8064;
#pragma unroll
        for (int dy = 0; dy < 3; dy++) {
#pragma unroll
            for (int dx = 0; dx < 3; dx++) {
                const int tap = dy * 3 + dx;
                unsigned afr[4][4];
#pragma unroll
                for (int mf = 0; mf < 4; mf++) {
                    const int ys = wm * 2 + (mf >> 1) + dy;
                    const int xb = (mf & 1) * 16 + g + dx;
                    afr[mf][0] = buf[(t * 10 + ys) * 36 + xb];
                    afr[mf][1] = buf[(t * 10 + ys) * 36 + xb + 8];
                    afr[mf][2] = buf[((t + 4) * 10 + ys) * 36 + xb];
                    afr[mf][3] = buf[((t + 4) * 10 + ys) * 36 + xb + 8];
                }
                unsigned bfr[8][2];
#pragma unroll
                for (int nf = 0; nf < 8; nf++) {
                    bfr[nf][0] = buf[2880 + (t * 9 + tap) * 72 + nf * 8 + g];
                    bfr[nf][1] = buf[2880 + ((t + 4) * 9 + tap) * 72 + nf * 8 + g];
                }
#pragma unroll
                for (int mf = 0; mf < 4; mf++)
#pragma unroll
                    for (int nf = 0; nf < 8; nf++)
                        mma_f16(acc[mf][nf], afr[mf], bfr[nf]);
            }
        }
        __syncthreads();
    }

#pragma unroll
    for (int mf = 0; mf < 4; mf++) {
        const int gy = r0 + wm * 2 + (mf >> 1);
        const int gxA = c0col + (mf & 1) * 16 + g;
        const int gxB = gxA + 8;
        const bool okA = gxA < kW, okB = gxB < kW;
#pragma unroll
        for (int nf = 0; nf < 8; nf++) {
            const int o = ob + nf * 8 + 2 * t;
            const float bv0 = bias[o], bv1 = bias[o + 1];
            float v00 = acc[mf][nf][0] + bv0;
            float v01 = acc[mf][nf][1] + bv1;
            float v10 = acc[mf][nf][2] + bv0;
            float v11 = acc[mf][nf][3] + bv1;
            if (PH == 0) {
                if (okA) {
                    __half* op = g_h1 + ((size_t)(b * kH + gy) * kW + gxA) * kHid + o;
                    op[0] = __float2half(0.5f * v00 * (1.f + erff(v00 * 0.70710678118654752f)));
                    op[1] = __float2half(0.5f * v01 * (1.f + erff(v01 * 0.70710678118654752f)));
                }
                if (okB) {
                    __half* op = g_h1 + ((size_t)(b * kH + gy) * kW + gxB) * kHid + o;
                    op[0] = __float2half(0.5f * v10 * (1.f + erff(v10 * 0.70710678118654752f)));
                    op[1] = __float2half(0.5f * v11 * (1.f + erff(v11 * 0.70710678118654752f)));
                }
            } else {
                const size_t base0 = ((size_t)(b * OC + o) * kH + gy) * kW;
                const size_t base1 = ((size_t)(b * OC + o + 1) * kH + gy) * kW;
                if (okA) {
                    outp[base0 + gxA] = v00 + g_x1[base0 + gxA];
                    outp[base1 + gxA] = v01 + g_x1[base1 + gxA];
                }
                if (okB) {
                    outp[base0 + gxB] = v10 + g_x1[base0 + gxB];
                    outp[base1 + gxB] = v11 + g_x1[base1 + gxB];
                }
            }
        }
    }
}

// ---------------- launch -----------------------------------------------------
extern "C" void kernel_launch(void* const* d_in, const int* in_sizes, int n_in,
                              void* d_out, int out_size) {
    (void)in_sizes; (void)n_in; (void)out_size;
    const float* x       = (const float*)d_in[0];
    const float* ln1_g   = (const float*)d_in[1];
    const float* ln1_b   = (const float*)d_in[2];
    const float* qkv_w   = (const float*)d_in[3];
    const float* qkv_b   = (const float*)d_in[4];
    const float* proj_w  = (const float*)d_in[5];
    const float* proj_b  = (const float*)d_in[6];
    const float* ln2_g   = (const float*)d_in[7];
    const float* ln2_b   = (const float*)d_in[8];
    const float* conv1_w = (const float*)d_in[9];
    const float* conv1_b = (const float*)d_in[10];
    const float* conv2_w = (const float*)d_in[11];
    const float* conv2_b = (const float*)d_in[12];
    float* out = (float*)d_out;

    constexpr int kConvSmem = 2 * 8064 * 4;   // 64512 B
    static bool attr_done = false;
    if (!attr_done) {
        cudaFuncSetAttribute(conv3x3_f16_kernel<0>, cudaFuncAttributeMaxDynamicSharedMemorySize, kConvSmem);
        cudaFuncSetAttribute(conv3x3_f16_kernel<1>, cudaFuncAttributeMaxDynamicSharedMemorySize, kConvSmem);
        attr_done = true;
    }

    wprep_kernel<0><<<(1327104 + 255) / 256, 256>>>(conv1_w);
    wprep_kernel<1><<<(1327104 + 255) / 256, 256>>>(conv2_w);
    wprep_gemm_kernel<0><<<(9 * 12 * 1024 + 255) / 256, 256>>>(qkv_w);
    wprep_gemm_kernel<1><<<(3 * 12 * 1024 + 255) / 256, 256>>>(proj_w);

    ln_kernel<0><<<kNT / 256, 256>>>(x, ln1_g, ln1_b);
    gemm_f16_kernel<0><<<dim3(kNT / 256, 9), 128>>>(qkv_b, nullptr);
    attn_kernel<<<kNWin * kHeads, 64>>>();
    gemm_f16_kernel<1><<<dim3(kNT / 256, 3), 128>>>(proj_b, x);
    ln_kernel<1><<<kNT / 256, 256>>>(nullptr, ln2_g, ln2_b);
    conv3x3_f16_kernel<0><<<dim3(14, 12, kB), 128, kConvSmem>>>(conv1_b, nullptr);
    conv3x3_f16_kernel<1><<<dim3(14, 3, kB), 128, kConvSmem>>>(conv2_b, out);
}